// round 2
// baseline (speedup 1.0000x reference)
#include <cuda_runtime.h>

// SpikingLayer LIF scan, GB300 sm_103a.
// Shapes: input (B*T, 2, N) fp32, output (B*T, N) fp32.
// B=32, T=1024, N=1024. Decays are exact powers of two:
//   syn: *0.75 (tau=5 -> dash=2), *0.5 (tau=2 -> dash=1); mem: *0.875 (tau=10 -> dash=3).
// x - x*2^-k == x*(1-2^-k) bitwise (both are the once-rounded exact value),
// so single-multiply decay matches the reference exactly. __fmul_rn/__fadd_rn
// prevent FMA contraction from flipping near-threshold spikes.

#define BATCH 32
#define TSTEPS 1024
#define NNEUR 1024
#define UNROLL 8

__global__ void __launch_bounds__(128, 4)
lif_scan_kernel(const float* __restrict__ in, float* __restrict__ out)
{
    const int n = blockIdx.x * blockDim.x + threadIdx.x;   // neuron index 0..1023
    const int b = blockIdx.y;                              // batch index 0..31

    // input element (b, t, s, n) at ((b*T + t)*2 + s)*N + n
    const long long base_in  = ((long long)b * TSTEPS) * (2LL * NNEUR) + n;
    const long long base_out = ((long long)b * TSTEPS) * (long long)NNEUR + n;

    float i0 = 0.0f, i1 = 0.0f, v = 0.0f;

    #pragma unroll 1
    for (int t = 0; t < TSTEPS; t += UNROLL) {
        float a0[UNROLL], a1[UNROLL];
        // Front-batched independent loads: MLP = 2*UNROLL per thread.
        #pragma unroll
        for (int u = 0; u < UNROLL; u++) {
            const long long off = base_in + (long long)(t + u) * (2LL * NNEUR);
            a0[u] = __ldcs(in + off);
            a1[u] = __ldcs(in + off + NNEUR);
        }
        #pragma unroll
        for (int u = 0; u < UNROLL; u++) {
            i0 = __fadd_rn(__fmul_rn(i0, 0.75f),  a0[u]);
            i1 = __fadd_rn(__fmul_rn(i1, 0.5f),   a1[u]);
            v  = __fadd_rn(__fmul_rn(v,  0.875f), __fadd_rn(i0, i1));
            float spk = (v >= 1.0f) ? 1.0f : 0.0f;
            v = __fadd_rn(v, -spk);
            __stcs(out + base_out + (long long)(t + u) * NNEUR, spk);
        }
    }
}

extern "C" void kernel_launch(void* const* d_in, const int* in_sizes, int n_in,
                              void* d_out, int out_size)
{
    const float* in = (const float*)d_in[0];
    float* out = (float*)d_out;
    (void)in_sizes; (void)n_in; (void)out_size;

    dim3 block(128, 1, 1);
    dim3 grid(NNEUR / 128, BATCH, 1);   // 8 x 32 = 256 CTAs, all co-resident
    lif_scan_kernel<<<grid, block>>>(in, out);
}

// round 3
// speedup vs baseline: 1.4821x; 1.4821x over previous
#include <cuda_runtime.h>

// SpikingLayer LIF scan, GB300 sm_103a.
// Input (B*T, 2, N) fp32, output (B*T, N) fp32. B=32, T=1024, N=1024.
// Decays exact powers of two -> single-rounded multiply form is bit-identical
// to the reference's subtract form. __fmul_rn/__fadd_rn block FMA contraction.
//
// R2: double-buffered prefetch (ping-pong register chunks) + UNROLL=16 to keep
// ~32 LDGs/thread continuously in flight (R1 sawtoothed at ~16 -> DRAM 40%).

#define BATCH 32
#define TSTEPS 1024
#define NNEUR 1024
#define U 16

__device__ __forceinline__ void lif_step(float& i0, float& i1, float& v,
                                         float a0, float a1, float& spk)
{
    i0 = __fadd_rn(__fmul_rn(i0, 0.75f),  a0);
    i1 = __fadd_rn(__fmul_rn(i1, 0.5f),   a1);
    v  = __fadd_rn(__fmul_rn(v,  0.875f), __fadd_rn(i0, i1));
    spk = (v >= 1.0f) ? 1.0f : 0.0f;
    v = __fadd_rn(v, -spk);
}

__global__ void __launch_bounds__(128)
lif_scan_kernel(const float* __restrict__ in, float* __restrict__ out)
{
    const int n = blockIdx.x * blockDim.x + threadIdx.x;   // neuron 0..1023
    const int b = blockIdx.y;                              // batch  0..31

    // element (b, t, s, n) at ((b*T + t)*2 + s)*N + n ; max offset < 2^27, int ok
    const float* __restrict__ pin  = in  + b * (TSTEPS * 2 * NNEUR) + n;
    float*       __restrict__ pout = out + b * (TSTEPS * NNEUR)     + n;

    float i0 = 0.0f, i1 = 0.0f, v = 0.0f, spk;
    float A0[U], A1[U], B0[U], B1[U];

    // Preload chunk 0 into A.
    #pragma unroll
    for (int u = 0; u < U; u++) {
        const int off = u * (2 * NNEUR);
        A0[u] = __ldcs(pin + off);
        A1[u] = __ldcs(pin + off + NNEUR);
    }

    #pragma unroll 1
    for (int t = 0; t < TSTEPS; t += 2 * U) {
        // Prefetch chunk (t+U) into B while A drains.
        #pragma unroll
        for (int u = 0; u < U; u++) {
            const int off = (t + U + u) * (2 * NNEUR);
            B0[u] = __ldcs(pin + off);
            B1[u] = __ldcs(pin + off + NNEUR);
        }
        // Compute + store chunk t from A.
        #pragma unroll
        for (int u = 0; u < U; u++) {
            lif_step(i0, i1, v, A0[u], A1[u], spk);
            __stcs(pout + (t + u) * NNEUR, spk);
        }
        // Prefetch chunk (t+2U) into A (skip past end).
        const int tp = t + 2 * U;
        if (tp < TSTEPS) {
            #pragma unroll
            for (int u = 0; u < U; u++) {
                const int off = (tp + u) * (2 * NNEUR);
                A0[u] = __ldcs(pin + off);
                A1[u] = __ldcs(pin + off + NNEUR);
            }
        }
        // Compute + store chunk t+U from B.
        #pragma unroll
        for (int u = 0; u < U; u++) {
            lif_step(i0, i1, v, B0[u], B1[u], spk);
            __stcs(pout + (t + U + u) * NNEUR, spk);
        }
    }
}

extern "C" void kernel_launch(void* const* d_in, const int* in_sizes, int n_in,
                              void* d_out, int out_size)
{
    const float* in = (const float*)d_in[0];
    float* out = (float*)d_out;
    (void)in_sizes; (void)n_in; (void)out_size;

    dim3 block(128, 1, 1);
    dim3 grid(NNEUR / 128, BATCH, 1);   // 256 CTAs, all co-resident
    lif_scan_kernel<<<grid, block>>>(in, out);
}

// round 4
// speedup vs baseline: 1.5212x; 1.0264x over previous
#include <cuda_runtime.h>

// SpikingLayer LIF scan, GB300 sm_103a.
// Input (B*T, 2, N) fp32, output (B*T, N) fp32. B=32, T=1024, N=1024.
// Decays exact powers of two -> single-rounded multiply form is bit-identical
// to the reference's subtract form. __fmul_rn/__fadd_rn block FMA contraction.
//
// R3: U=32 ping-pong buffers -> 64 warp-LDGs issued per burst, pinning the
// per-warp outstanding-load queue at its ~55 cap => ~48 KB/SM in flight
// (R2's 28 KB gave only 61% DRAM). 2U=64 divides T exactly.

#define BATCH 32
#define TSTEPS 1024
#define NNEUR 1024
#define U 32

__device__ __forceinline__ void lif_step(float& i0, float& i1, float& v,
                                         float a0, float a1, float& spk)
{
    i0 = __fadd_rn(__fmul_rn(i0, 0.75f),  a0);
    i1 = __fadd_rn(__fmul_rn(i1, 0.5f),   a1);
    v  = __fadd_rn(__fmul_rn(v,  0.875f), __fadd_rn(i0, i1));
    spk = (v >= 1.0f) ? 1.0f : 0.0f;
    v = __fadd_rn(v, -spk);
}

__global__ void __launch_bounds__(128)
lif_scan_kernel(const float* __restrict__ in, float* __restrict__ out)
{
    const int n = blockIdx.x * blockDim.x + threadIdx.x;   // neuron 0..1023
    const int b = blockIdx.y;                              // batch  0..31

    // element (b, t, s, n) at ((b*T + t)*2 + s)*N + n ; offsets < 2^27, int ok
    const float* __restrict__ pin  = in  + b * (TSTEPS * 2 * NNEUR) + n;
    float*       __restrict__ pout = out + b * (TSTEPS * NNEUR)     + n;

    float i0 = 0.0f, i1 = 0.0f, v = 0.0f, spk;
    float A0[U], A1[U], B0[U], B1[U];

    // Preload chunk 0 into A.
    #pragma unroll
    for (int u = 0; u < U; u++) {
        const int off = u * (2 * NNEUR);
        A0[u] = __ldcs(pin + off);
        A1[u] = __ldcs(pin + off + NNEUR);
    }

    #pragma unroll 1
    for (int t = 0; t < TSTEPS; t += 2 * U) {
        // Prefetch chunk (t+U) into B; warp parks at the outstanding-LDG cap.
        #pragma unroll
        for (int u = 0; u < U; u++) {
            const int off = (t + U + u) * (2 * NNEUR);
            B0[u] = __ldcs(pin + off);
            B1[u] = __ldcs(pin + off + NNEUR);
        }
        // Compute + store chunk t from A.
        #pragma unroll
        for (int u = 0; u < U; u++) {
            lif_step(i0, i1, v, A0[u], A1[u], spk);
            __stcs(pout + (t + u) * NNEUR, spk);
        }
        // Prefetch chunk (t+2U) into A (last iteration skips past end).
        const int tp = t + 2 * U;
        if (tp < TSTEPS) {
            #pragma unroll
            for (int u = 0; u < U; u++) {
                const int off = (tp + u) * (2 * NNEUR);
                A0[u] = __ldcs(pin + off);
                A1[u] = __ldcs(pin + off + NNEUR);
            }
        }
        // Compute + store chunk t+U from B.
        #pragma unroll
        for (int u = 0; u < U; u++) {
            lif_step(i0, i1, v, B0[u], B1[u], spk);
            __stcs(pout + (t + U + u) * NNEUR, spk);
        }
    }
}

extern "C" void kernel_launch(void* const* d_in, const int* in_sizes, int n_in,
                              void* d_out, int out_size)
{
    const float* in = (const float*)d_in[0];
    float* out = (float*)d_out;
    (void)in_sizes; (void)n_in; (void)out_size;

    dim3 block(128, 1, 1);
    dim3 grid(NNEUR / 128, BATCH, 1);   // 256 CTAs, all co-resident
    lif_scan_kernel<<<grid, block>>>(in, out);
}

// round 5
// speedup vs baseline: 1.6464x; 1.0823x over previous
#include <cuda_runtime.h>
#include <cstdint>

// SpikingLayer LIF scan, GB300 sm_103a — R4: cp.async.bulk (TMA-path) pipeline.
// The LDG path saturates at ~62% DRAM due to the per-SM in-flight line cap
// (~248 L1tex wavefronts = 31.7 KB) at our fixed 6.9 warps/SM. Bulk-async
// copies are tracked in the async proxy (no per-warp/per-SM LDG queue cap),
// letting ~136 KB/SM of reads stay in flight.
// Scan math unchanged (single-rounded multiply decay == reference subtract
// form bitwise; __fmul_rn/__fadd_rn block FMA contraction).

#define BATCH   32
#define TSTEPS  1024
#define NNEUR   1024
#define CTA_N   128
#define TCHUNK  16
#define STAGES  6
#define NCHUNKS (TSTEPS / TCHUNK)                  // 64
#define STAGE_FLOATS (TCHUNK * 2 * CTA_N)          // 4096 floats
#define STAGE_BYTES  (STAGE_FLOATS * 4)            // 16 KB
#define DYN_SMEM     (STAGES * STAGE_BYTES)        // 96 KB

extern __shared__ float sdata[];

__device__ __forceinline__ void issue_chunk(uint32_t mb, uint32_t dst,
                                            const char* src)
{
    asm volatile("mbarrier.arrive.expect_tx.shared::cta.b64 _, [%0], %1;"
                 :: "r"(mb), "r"(STAGE_BYTES) : "memory");
    #pragma unroll
    for (int r = 0; r < TCHUNK * 2; r++) {
        const int tl = r >> 1, sy = r & 1;
        asm volatile(
            "cp.async.bulk.shared::cta.global.mbarrier::complete_tx::bytes "
            "[%0], [%1], %2, [%3];"
            :: "r"(dst + r * (CTA_N * 4)),
               "l"(src + (size_t)tl * (2 * NNEUR * 4) + (size_t)sy * (NNEUR * 4)),
               "r"(CTA_N * 4), "r"(mb)
            : "memory");
    }
}

__global__ void __launch_bounds__(CTA_N)
lif_scan_tma(const float* __restrict__ in, float* __restrict__ out)
{
    __shared__ __align__(8) uint64_t mbar[STAGES];

    const int tid = threadIdx.x;
    const int nb  = blockIdx.x;     // neuron block 0..7
    const int b   = blockIdx.y;     // batch 0..31

    const char* gbase = (const char*)in
                      + (size_t)b  * ((size_t)TSTEPS * 2 * NNEUR * 4)
                      + (size_t)nb * (CTA_N * 4);
    float* pout = out + (b * TSTEPS) * NNEUR + nb * CTA_N + tid;

    const uint32_t mb0 = (uint32_t)__cvta_generic_to_shared(&mbar[0]);
    const uint32_t sd0 = (uint32_t)__cvta_generic_to_shared(sdata);

    if (tid == 0) {
        #pragma unroll
        for (int s = 0; s < STAGES; s++)
            asm volatile("mbarrier.init.shared::cta.b64 [%0], 1;"
                         :: "r"(mb0 + s * 8) : "memory");
    }
    __syncthreads();

    // Prologue: fill all stages.
    if (tid == 0) {
        #pragma unroll
        for (int c = 0; c < STAGES; c++)
            issue_chunk(mb0 + c * 8, sd0 + c * STAGE_BYTES,
                        gbase + (size_t)c * (TCHUNK * 2 * NNEUR * 4));
    }

    float i0 = 0.0f, i1 = 0.0f, v = 0.0f;

    #pragma unroll 1
    for (int c = 0; c < NCHUNKS; c++) {
        const int st = c % STAGES;
        const uint32_t ph = (uint32_t)(c / STAGES) & 1u;
        const uint32_t mb = mb0 + st * 8;

        // Wait stage full (acquire orders the async-proxy smem writes).
        uint32_t done = 0;
        while (!done) {
            asm volatile(
                "{\n\t.reg .pred p;\n\t"
                "mbarrier.try_wait.parity.acquire.cta.shared::cta.b64 p, [%1], %2, 0x989680;\n\t"
                "selp.b32 %0, 1, 0, p;\n\t}"
                : "=r"(done) : "r"(mb), "r"(ph) : "memory");
        }

        const float* sf = sdata + st * STAGE_FLOATS;
        #pragma unroll
        for (int tl = 0; tl < TCHUNK; tl++) {
            const float a0 = sf[(tl * 2    ) * CTA_N + tid];
            const float a1 = sf[(tl * 2 + 1) * CTA_N + tid];
            i0 = __fadd_rn(__fmul_rn(i0, 0.75f),  a0);
            i1 = __fadd_rn(__fmul_rn(i1, 0.5f),   a1);
            v  = __fadd_rn(__fmul_rn(v,  0.875f), __fadd_rn(i0, i1));
            const float spk = (v >= 1.0f) ? 1.0f : 0.0f;
            v = __fadd_rn(v, -spk);
            __stcs(pout + (c * TCHUNK + tl) * NNEUR, spk);
        }
        __syncthreads();   // all warps done reading stage st

        const int cn = c + STAGES;
        if (tid == 0 && cn < NCHUNKS)
            issue_chunk(mb, sd0 + st * STAGE_BYTES,
                        gbase + (size_t)cn * (TCHUNK * 2 * NNEUR * 4));
    }
}

extern "C" void kernel_launch(void* const* d_in, const int* in_sizes, int n_in,
                              void* d_out, int out_size)
{
    const float* in = (const float*)d_in[0];
    float* out = (float*)d_out;
    (void)in_sizes; (void)n_in; (void)out_size;

    cudaFuncSetAttribute(lif_scan_tma,
                         cudaFuncAttributeMaxDynamicSharedMemorySize, DYN_SMEM);

    dim3 block(CTA_N, 1, 1);
    dim3 grid(NNEUR / CTA_N, BATCH, 1);   // 8 x 32 = 256 CTAs
    lif_scan_tma<<<grid, block, DYN_SMEM>>>(in, out);
}

// round 7
// speedup vs baseline: 1.7790x; 1.0805x over previous
#include <cuda_runtime.h>
#include <cuda.h>
#include <cstdint>

// SpikingLayer LIF scan, GB300 sm_103a — R6: 2D-tensormap TMA pipeline.
// R5 faulted: cp.async.bulk.tensor requires 128B-aligned SMEM destination and
// the unadorned extern-shared base isn't guaranteed that. Fix: __align__(1024)
// on the dynamic smem block (stages are 16 KB apart -> all dests aligned);
// drop prefetch.tensormap (param-space pointer, not needed).
// Theory unchanged: one 16 KB UTMALDG per stage (box 128x32, 4 KB row stride
// handled by the engine) removes the per-request copy-engine overhead that
// capped R4 at 63% DRAM.
// Scan math: single-rounded multiply decay == reference subtract form bitwise;
// __fmul_rn/__fadd_rn block FMA contraction.

#define BATCH   32
#define TSTEPS  1024
#define NNEUR   1024
#define CTA_N   128
#define TCHUNK  16
#define STAGES  6
#define NCHUNKS (TSTEPS / TCHUNK)                  // 64
#define ROWS_PER_CHUNK (TCHUNK * 2)                // 32
#define STAGE_FLOATS (ROWS_PER_CHUNK * CTA_N)      // 4096
#define STAGE_BYTES  (STAGE_FLOATS * 4)            // 16 KB
#define DYN_SMEM     (STAGES * STAGE_BYTES)        // 96 KB

extern __shared__ __align__(1024) char smem_raw[];

// ---------------- R6 kernel: one 2D TMA load per stage ----------------

__global__ void __launch_bounds__(CTA_N)
lif_scan_tmap(const __grid_constant__ CUtensorMap tmap,
              float* __restrict__ out)
{
    __shared__ __align__(8) uint64_t mbar[STAGES];
    float* sdata = reinterpret_cast<float*>(smem_raw);

    const int tid = threadIdx.x;
    const int nb  = blockIdx.x;     // neuron block 0..7
    const int b   = blockIdx.y;     // batch 0..31

    float* pout = out + (b * TSTEPS) * NNEUR + nb * CTA_N + tid;

    const uint32_t mb0 = (uint32_t)__cvta_generic_to_shared(&mbar[0]);
    const uint32_t sd0 = (uint32_t)__cvta_generic_to_shared(sdata);
    const int x0 = nb * CTA_N;                 // column coord (elements)
    const int ybase = b * (TSTEPS * 2);        // first row of this batch

    if (tid == 0) {
        #pragma unroll
        for (int s = 0; s < STAGES; s++)
            asm volatile("mbarrier.init.shared::cta.b64 [%0], 1;"
                         :: "r"(mb0 + s * 8) : "memory");
    }
    __syncthreads();

    // Prologue: fill all stages.
    if (tid == 0) {
        #pragma unroll
        for (int c = 0; c < STAGES; c++) {
            const uint32_t mb = mb0 + c * 8;
            asm volatile("mbarrier.arrive.expect_tx.shared::cta.b64 _, [%0], %1;"
                         :: "r"(mb), "r"(STAGE_BYTES) : "memory");
            asm volatile(
                "cp.async.bulk.tensor.2d.shared::cta.global.tile"
                ".mbarrier::complete_tx::bytes [%0], [%1, {%2, %3}], [%4];"
                :: "r"(sd0 + c * STAGE_BYTES), "l"(&tmap),
                   "r"(x0), "r"(ybase + c * ROWS_PER_CHUNK), "r"(mb)
                : "memory");
        }
    }

    float i0 = 0.0f, i1 = 0.0f, v = 0.0f;

    #pragma unroll 1
    for (int c = 0; c < NCHUNKS; c++) {
        const int st = c % STAGES;
        const uint32_t ph = (uint32_t)(c / STAGES) & 1u;
        const uint32_t mb = mb0 + st * 8;

        uint32_t done = 0;
        while (!done) {
            asm volatile(
                "{\n\t.reg .pred p;\n\t"
                "mbarrier.try_wait.parity.acquire.cta.shared::cta.b64 p, [%1], %2, 0x989680;\n\t"
                "selp.b32 %0, 1, 0, p;\n\t}"
                : "=r"(done) : "r"(mb), "r"(ph) : "memory");
        }

        const float* sf = sdata + st * STAGE_FLOATS;
        #pragma unroll
        for (int tl = 0; tl < TCHUNK; tl++) {
            const float a0 = sf[(tl * 2    ) * CTA_N + tid];
            const float a1 = sf[(tl * 2 + 1) * CTA_N + tid];
            i0 = __fadd_rn(__fmul_rn(i0, 0.75f),  a0);
            i1 = __fadd_rn(__fmul_rn(i1, 0.5f),   a1);
            v  = __fadd_rn(__fmul_rn(v,  0.875f), __fadd_rn(i0, i1));
            const float spk = (v >= 1.0f) ? 1.0f : 0.0f;
            v = __fadd_rn(v, -spk);
            __stcs(pout + (c * TCHUNK + tl) * NNEUR, spk);
        }
        __syncthreads();   // all warps done reading stage st

        const int cn = c + STAGES;
        if (tid == 0 && cn < NCHUNKS) {
            asm volatile("mbarrier.arrive.expect_tx.shared::cta.b64 _, [%0], %1;"
                         :: "r"(mb), "r"(STAGE_BYTES) : "memory");
            asm volatile(
                "cp.async.bulk.tensor.2d.shared::cta.global.tile"
                ".mbarrier::complete_tx::bytes [%0], [%1, {%2, %3}], [%4];"
                :: "r"(sd0 + st * STAGE_BYTES), "l"(&tmap),
                   "r"(x0), "r"(ybase + cn * ROWS_PER_CHUNK), "r"(mb)
                : "memory");
        }
    }
}

// ---------------- Fallback (R4 path): 1D bulk copies, known-correct ----------------

__device__ __forceinline__ void issue_chunk_1d(uint32_t mb, uint32_t dst,
                                               const char* src)
{
    asm volatile("mbarrier.arrive.expect_tx.shared::cta.b64 _, [%0], %1;"
                 :: "r"(mb), "r"(STAGE_BYTES) : "memory");
    #pragma unroll
    for (int r = 0; r < ROWS_PER_CHUNK; r++) {
        const int tl = r >> 1, sy = r & 1;
        asm volatile(
            "cp.async.bulk.shared::cta.global.mbarrier::complete_tx::bytes "
            "[%0], [%1], %2, [%3];"
            :: "r"(dst + r * (CTA_N * 4)),
               "l"(src + (size_t)tl * (2 * NNEUR * 4) + (size_t)sy * (NNEUR * 4)),
               "r"(CTA_N * 4), "r"(mb)
            : "memory");
    }
}

__global__ void __launch_bounds__(CTA_N)
lif_scan_bulk(const float* __restrict__ in, float* __restrict__ out)
{
    __shared__ __align__(8) uint64_t mbar[STAGES];
    float* sdata = reinterpret_cast<float*>(smem_raw);

    const int tid = threadIdx.x;
    const int nb  = blockIdx.x;
    const int b   = blockIdx.y;

    const char* gbase = (const char*)in
                      + (size_t)b  * ((size_t)TSTEPS * 2 * NNEUR * 4)
                      + (size_t)nb * (CTA_N * 4);
    float* pout = out + (b * TSTEPS) * NNEUR + nb * CTA_N + tid;

    const uint32_t mb0 = (uint32_t)__cvta_generic_to_shared(&mbar[0]);
    const uint32_t sd0 = (uint32_t)__cvta_generic_to_shared(sdata);

    if (tid == 0) {
        #pragma unroll
        for (int s = 0; s < STAGES; s++)
            asm volatile("mbarrier.init.shared::cta.b64 [%0], 1;"
                         :: "r"(mb0 + s * 8) : "memory");
    }
    __syncthreads();

    if (tid == 0) {
        #pragma unroll
        for (int c = 0; c < STAGES; c++)
            issue_chunk_1d(mb0 + c * 8, sd0 + c * STAGE_BYTES,
                           gbase + (size_t)c * (TCHUNK * 2 * NNEUR * 4));
    }

    float i0 = 0.0f, i1 = 0.0f, v = 0.0f;

    #pragma unroll 1
    for (int c = 0; c < NCHUNKS; c++) {
        const int st = c % STAGES;
        const uint32_t ph = (uint32_t)(c / STAGES) & 1u;
        const uint32_t mb = mb0 + st * 8;

        uint32_t done = 0;
        while (!done) {
            asm volatile(
                "{\n\t.reg .pred p;\n\t"
                "mbarrier.try_wait.parity.acquire.cta.shared::cta.b64 p, [%1], %2, 0x989680;\n\t"
                "selp.b32 %0, 1, 0, p;\n\t}"
                : "=r"(done) : "r"(mb), "r"(ph) : "memory");
        }

        const float* sf = sdata + st * STAGE_FLOATS;
        #pragma unroll
        for (int tl = 0; tl < TCHUNK; tl++) {
            const float a0 = sf[(tl * 2    ) * CTA_N + tid];
            const float a1 = sf[(tl * 2 + 1) * CTA_N + tid];
            i0 = __fadd_rn(__fmul_rn(i0, 0.75f),  a0);
            i1 = __fadd_rn(__fmul_rn(i1, 0.5f),   a1);
            v  = __fadd_rn(__fmul_rn(v,  0.875f), __fadd_rn(i0, i1));
            const float spk = (v >= 1.0f) ? 1.0f : 0.0f;
            v = __fadd_rn(v, -spk);
            __stcs(pout + (c * TCHUNK + tl) * NNEUR, spk);
        }
        __syncthreads();

        const int cn = c + STAGES;
        if (tid == 0 && cn < NCHUNKS)
            issue_chunk_1d(mb, sd0 + st * STAGE_BYTES,
                           gbase + (size_t)cn * (TCHUNK * 2 * NNEUR * 4));
    }
}

// ---------------- host ----------------

typedef CUresult (*PFN_encodeTiled)(
    CUtensorMap*, CUtensorMapDataType, cuuint32_t, void*,
    const cuuint64_t*, const cuuint64_t*, const cuuint32_t*, const cuuint32_t*,
    CUtensorMapInterleave, CUtensorMapSwizzle, CUtensorMapL2promotion,
    CUtensorMapFloatOOBfill);

extern "C" void kernel_launch(void* const* d_in, const int* in_sizes, int n_in,
                              void* d_out, int out_size)
{
    const float* in = (const float*)d_in[0];
    float* out = (float*)d_out;
    (void)in_sizes; (void)n_in; (void)out_size;

    dim3 block(CTA_N, 1, 1);
    dim3 grid(NNEUR / CTA_N, BATCH, 1);   // 8 x 32 = 256 CTAs

    // Resolve cuTensorMapEncodeTiled through the runtime (no -lcuda needed).
    PFN_encodeTiled encode = nullptr;
    cudaDriverEntryPointQueryResult qres = cudaDriverEntryPointSymbolNotFound;
    if (cudaGetDriverEntryPointByVersion("cuTensorMapEncodeTiled",
                                         (void**)&encode, 12000,
                                         cudaEnableDefault, &qres) != cudaSuccess
        || qres != cudaDriverEntryPointSuccess)
        encode = nullptr;

    bool use_tmap = false;
    CUtensorMap tmap;
    if (encode) {
        // Input viewed 2D: width 1024 f32 (4 KB rows), height B*T*2 rows.
        cuuint64_t dims[2]    = {NNEUR, (cuuint64_t)BATCH * TSTEPS * 2};
        cuuint64_t strides[1] = {NNEUR * sizeof(float)};
        cuuint32_t box[2]     = {CTA_N, ROWS_PER_CHUNK};   // 512 B x 32 rows
        cuuint32_t estr[2]    = {1, 1};
        CUresult r = encode(&tmap, CU_TENSOR_MAP_DATA_TYPE_FLOAT32, 2,
                            (void*)in, dims, strides, box, estr,
                            CU_TENSOR_MAP_INTERLEAVE_NONE,
                            CU_TENSOR_MAP_SWIZZLE_NONE,
                            CU_TENSOR_MAP_L2_PROMOTION_L2_128B,
                            CU_TENSOR_MAP_FLOAT_OOB_FILL_NONE);
        use_tmap = (r == CUDA_SUCCESS);
    }

    if (use_tmap) {
        cudaFuncSetAttribute(lif_scan_tmap,
                             cudaFuncAttributeMaxDynamicSharedMemorySize, DYN_SMEM);
        lif_scan_tmap<<<grid, block, DYN_SMEM>>>(tmap, out);
    } else {
        cudaFuncSetAttribute(lif_scan_bulk,
                             cudaFuncAttributeMaxDynamicSharedMemorySize, DYN_SMEM);
        lif_scan_bulk<<<grid, block, DYN_SMEM>>>(in, out);
    }
}

// round 10
// speedup vs baseline: 1.8420x; 1.0354x over previous
#include <cuda_runtime.h>
#include <cuda.h>
#include <cstdint>

// SpikingLayer LIF scan, GB300 sm_103a — R7: wider TMA box rows.
// R6 analysis: TMA engine pays ~30 cyc per box *row*; 512 B rows cap read
// supply at ~17 B/cyc/SM -> DRAM stuck at 78%. Fix: CTA covers 256 neurons
// (256 threads), box {256,32} -> 1 KB rows, 32 KB/stage, supply ~34 B/cyc/SM.
// Grid 4x32 = 128 CTAs, 1/SM, 6 stages = 192 KB smem (~160 KB reads in
// flight per SM). Scan math unchanged (single-rounded multiply decay ==
// reference subtract form bitwise; __fmul_rn/__fadd_rn block FMA contraction).

#define BATCH   32
#define TSTEPS  1024
#define NNEUR   1024
#define CTA_N   256
#define TCHUNK  16
#define STAGES  6
#define NCHUNKS (TSTEPS / TCHUNK)                  // 64
#define ROWS_PER_CHUNK (TCHUNK * 2)                // 32
#define STAGE_FLOATS (ROWS_PER_CHUNK * CTA_N)      // 8192
#define STAGE_BYTES  (STAGE_FLOATS * 4)            // 32 KB
#define DYN_SMEM     (STAGES * STAGE_BYTES)        // 192 KB

extern __shared__ __align__(1024) char smem_raw[];

// ---------------- main kernel: one 2D TMA load (1 KB rows) per stage ----------------

__global__ void __launch_bounds__(CTA_N)
lif_scan_tmap(const __grid_constant__ CUtensorMap tmap,
              float* __restrict__ out)
{
    __shared__ __align__(8) uint64_t mbar[STAGES];
    float* sdata = reinterpret_cast<float*>(smem_raw);

    const int tid = threadIdx.x;
    const int nb  = blockIdx.x;     // neuron block 0..3
    const int b   = blockIdx.y;     // batch 0..31

    float* pout = out + (b * TSTEPS) * NNEUR + nb * CTA_N + tid;

    const uint32_t mb0 = (uint32_t)__cvta_generic_to_shared(&mbar[0]);
    const uint32_t sd0 = (uint32_t)__cvta_generic_to_shared(sdata);
    const int x0 = nb * CTA_N;                 // column coord (elements)
    const int ybase = b * (TSTEPS * 2);        // first row of this batch

    if (tid == 0) {
        #pragma unroll
        for (int s = 0; s < STAGES; s++)
            asm volatile("mbarrier.init.shared::cta.b64 [%0], 1;"
                         :: "r"(mb0 + s * 8) : "memory");
    }
    __syncthreads();

    // Prologue: fill all stages.
    if (tid == 0) {
        #pragma unroll
        for (int c = 0; c < STAGES; c++) {
            const uint32_t mb = mb0 + c * 8;
            asm volatile("mbarrier.arrive.expect_tx.shared::cta.b64 _, [%0], %1;"
                         :: "r"(mb), "r"(STAGE_BYTES) : "memory");
            asm volatile(
                "cp.async.bulk.tensor.2d.shared::cta.global.tile"
                ".mbarrier::complete_tx::bytes [%0], [%1, {%2, %3}], [%4];"
                :: "r"(sd0 + c * STAGE_BYTES), "l"(&tmap),
                   "r"(x0), "r"(ybase + c * ROWS_PER_CHUNK), "r"(mb)
                : "memory");
        }
    }

    float i0 = 0.0f, i1 = 0.0f, v = 0.0f;

    #pragma unroll 1
    for (int c = 0; c < NCHUNKS; c++) {
        const int st = c % STAGES;
        const uint32_t ph = (uint32_t)(c / STAGES) & 1u;
        const uint32_t mb = mb0 + st * 8;

        uint32_t done = 0;
        while (!done) {
            asm volatile(
                "{\n\t.reg .pred p;\n\t"
                "mbarrier.try_wait.parity.acquire.cta.shared::cta.b64 p, [%1], %2, 0x989680;\n\t"
                "selp.b32 %0, 1, 0, p;\n\t}"
                : "=r"(done) : "r"(mb), "r"(ph) : "memory");
        }

        const float* sf = sdata + st * STAGE_FLOATS;
        #pragma unroll
        for (int tl = 0; tl < TCHUNK; tl++) {
            const float a0 = sf[(tl * 2    ) * CTA_N + tid];
            const float a1 = sf[(tl * 2 + 1) * CTA_N + tid];
            i0 = __fadd_rn(__fmul_rn(i0, 0.75f),  a0);
            i1 = __fadd_rn(__fmul_rn(i1, 0.5f),   a1);
            v  = __fadd_rn(__fmul_rn(v,  0.875f), __fadd_rn(i0, i1));
            const float spk = (v >= 1.0f) ? 1.0f : 0.0f;
            v = __fadd_rn(v, -spk);
            __stcs(pout + (c * TCHUNK + tl) * NNEUR, spk);
        }
        __syncthreads();   // all warps done reading stage st

        const int cn = c + STAGES;
        if (tid == 0 && cn < NCHUNKS) {
            asm volatile("mbarrier.arrive.expect_tx.shared::cta.b64 _, [%0], %1;"
                         :: "r"(mb), "r"(STAGE_BYTES) : "memory");
            asm volatile(
                "cp.async.bulk.tensor.2d.shared::cta.global.tile"
                ".mbarrier::complete_tx::bytes [%0], [%1, {%2, %3}], [%4];"
                :: "r"(sd0 + st * STAGE_BYTES), "l"(&tmap),
                   "r"(x0), "r"(ybase + cn * ROWS_PER_CHUNK), "r"(mb)
                : "memory");
        }
    }
}

// ---------------- Fallback: 1D bulk copies (no tensormap needed) ----------------

__device__ __forceinline__ void issue_chunk_1d(uint32_t mb, uint32_t dst,
                                               const char* src)
{
    asm volatile("mbarrier.arrive.expect_tx.shared::cta.b64 _, [%0], %1;"
                 :: "r"(mb), "r"(STAGE_BYTES) : "memory");
    #pragma unroll
    for (int r = 0; r < ROWS_PER_CHUNK; r++) {
        asm volatile(
            "cp.async.bulk.shared::cta.global.mbarrier::complete_tx::bytes "
            "[%0], [%1], %2, [%3];"
            :: "r"(dst + r * (CTA_N * 4)),
               "l"(src + (size_t)r * (NNEUR * 4)),
               "r"(CTA_N * 4), "r"(mb)
            : "memory");
    }
}

__global__ void __launch_bounds__(CTA_N)
lif_scan_bulk(const float* __restrict__ in, float* __restrict__ out)
{
    __shared__ __align__(8) uint64_t mbar[STAGES];
    float* sdata = reinterpret_cast<float*>(smem_raw);

    const int tid = threadIdx.x;
    const int nb  = blockIdx.x;
    const int b   = blockIdx.y;

    const char* gbase = (const char*)in
                      + (size_t)b  * ((size_t)TSTEPS * 2 * NNEUR * 4)
                      + (size_t)nb * (CTA_N * 4);
    float* pout = out + (b * TSTEPS) * NNEUR + nb * CTA_N + tid;

    const uint32_t mb0 = (uint32_t)__cvta_generic_to_shared(&mbar[0]);
    const uint32_t sd0 = (uint32_t)__cvta_generic_to_shared(sdata);

    if (tid == 0) {
        #pragma unroll
        for (int s = 0; s < STAGES; s++)
            asm volatile("mbarrier.init.shared::cta.b64 [%0], 1;"
                         :: "r"(mb0 + s * 8) : "memory");
    }
    __syncthreads();

    if (tid == 0) {
        #pragma unroll
        for (int c = 0; c < STAGES; c++)
            issue_chunk_1d(mb0 + c * 8, sd0 + c * STAGE_BYTES,
                           gbase + (size_t)c * (ROWS_PER_CHUNK * NNEUR * 4));
    }

    float i0 = 0.0f, i1 = 0.0f, v = 0.0f;

    #pragma unroll 1
    for (int c = 0; c < NCHUNKS; c++) {
        const int st = c % STAGES;
        const uint32_t ph = (uint32_t)(c / STAGES) & 1u;
        const uint32_t mb = mb0 + st * 8;

        uint32_t done = 0;
        while (!done) {
            asm volatile(
                "{\n\t.reg .pred p;\n\t"
                "mbarrier.try_wait.parity.acquire.cta.shared::cta.b64 p, [%1], %2, 0x989680;\n\t"
                "selp.b32 %0, 1, 0, p;\n\t}"
                : "=r"(done) : "r"(mb), "r"(ph) : "memory");
        }

        const float* sf = sdata + st * STAGE_FLOATS;
        #pragma unroll
        for (int tl = 0; tl < TCHUNK; tl++) {
            const float a0 = sf[(tl * 2    ) * CTA_N + tid];
            const float a1 = sf[(tl * 2 + 1) * CTA_N + tid];
            i0 = __fadd_rn(__fmul_rn(i0, 0.75f),  a0);
            i1 = __fadd_rn(__fmul_rn(i1, 0.5f),   a1);
            v  = __fadd_rn(__fmul_rn(v,  0.875f), __fadd_rn(i0, i1));
            const float spk = (v >= 1.0f) ? 1.0f : 0.0f;
            v = __fadd_rn(v, -spk);
            __stcs(pout + (c * TCHUNK + tl) * NNEUR, spk);
        }
        __syncthreads();

        const int cn = c + STAGES;
        if (tid == 0 && cn < NCHUNKS)
            issue_chunk_1d(mb, sd0 + st * STAGE_BYTES,
                           gbase + (size_t)cn * (ROWS_PER_CHUNK * NNEUR * 4));
    }
}

// ---------------- host ----------------

typedef CUresult (*PFN_encodeTiled)(
    CUtensorMap*, CUtensorMapDataType, cuuint32_t, void*,
    const cuuint64_t*, const cuuint64_t*, const cuuint32_t*, const cuuint32_t*,
    CUtensorMapInterleave, CUtensorMapSwizzle, CUtensorMapL2promotion,
    CUtensorMapFloatOOBfill);

extern "C" void kernel_launch(void* const* d_in, const int* in_sizes, int n_in,
                              void* d_out, int out_size)
{
    const float* in = (const float*)d_in[0];
    float* out = (float*)d_out;
    (void)in_sizes; (void)n_in; (void)out_size;

    dim3 block(CTA_N, 1, 1);
    dim3 grid(NNEUR / CTA_N, BATCH, 1);   // 4 x 32 = 128 CTAs, 1 per SM

    PFN_encodeTiled encode = nullptr;
    cudaDriverEntryPointQueryResult qres = cudaDriverEntryPointSymbolNotFound;
    if (cudaGetDriverEntryPointByVersion("cuTensorMapEncodeTiled",
                                         (void**)&encode, 12000,
                                         cudaEnableDefault, &qres) != cudaSuccess
        || qres != cudaDriverEntryPointSuccess)
        encode = nullptr;

    bool use_tmap = false;
    CUtensorMap tmap;
    if (encode) {
        // Input viewed 2D: width 1024 f32 (4 KB rows), height B*T*2 rows.
        cuuint64_t dims[2]    = {NNEUR, (cuuint64_t)BATCH * TSTEPS * 2};
        cuuint64_t strides[1] = {NNEUR * sizeof(float)};
        cuuint32_t box[2]     = {CTA_N, ROWS_PER_CHUNK};   // 1 KB x 32 rows
        cuuint32_t estr[2]    = {1, 1};
        CUresult r = encode(&tmap, CU_TENSOR_MAP_DATA_TYPE_FLOAT32, 2,
                            (void*)in, dims, strides, box, estr,
                            CU_TENSOR_MAP_INTERLEAVE_NONE,
                            CU_TENSOR_MAP_SWIZZLE_NONE,
                            CU_TENSOR_MAP_L2_PROMOTION_L2_128B,
                            CU_TENSOR_MAP_FLOAT_OOB_FILL_NONE);
        use_tmap = (r == CUDA_SUCCESS);
    }

    if (use_tmap) {
        cudaFuncSetAttribute(lif_scan_tmap,
                             cudaFuncAttributeMaxDynamicSharedMemorySize, DYN_SMEM);
        lif_scan_tmap<<<grid, block, DYN_SMEM>>>(tmap, out);
    } else {
        cudaFuncSetAttribute(lif_scan_bulk,
                             cudaFuncAttributeMaxDynamicSharedMemorySize, DYN_SMEM);
        lif_scan_bulk<<<grid, block, DYN_SMEM>>>(in, out);
    }
}